// round 1
// baseline (speedup 1.0000x reference)
#include <cuda_runtime.h>
#include <math_constants.h>

// Problem constants (fixed shapes from setup_inputs)
#define BATCH 8
#define SEQ   2048
#define DQ    512
#define DKV   768
#define HDIM  512
#define MROWS (BATCH*SEQ)   // 16384

// GEMM tiling
#define BM 128
#define BN 128
#define BK 8
#define TM 8
#define TN 8

// -------- scratch (static device globals; no runtime allocation) --------
__device__ float g_Q[(size_t)MROWS * HDIM];             // 33.5 MB
__device__ float g_K[(size_t)MROWS * HDIM];             // 33.5 MB
__device__ float g_V[(size_t)MROWS * DQ];               // 33.5 MB
__device__ float g_S[(size_t)BATCH * SEQ * SEQ];        // 134 MB

// ===================== GEMM: C = A[M,K] * B[K,N] + bias =====================
__global__ __launch_bounds__(256) void gemm_bias_nn(
    const float* __restrict__ A, const float* __restrict__ B,
    const float* __restrict__ bias, float* __restrict__ C,
    int M, int N, int K)
{
    __shared__ float As[BK][BM];
    __shared__ float Bs[BK][BN];
    const int tid = threadIdx.x;
    const int m0 = blockIdx.y * BM;
    const int n0 = blockIdx.x * BN;
    const int tx = tid & 15;
    const int ty = tid >> 4;

    float acc[TM][TN];
#pragma unroll
    for (int i = 0; i < TM; i++)
#pragma unroll
        for (int j = 0; j < TN; j++) acc[i][j] = 0.f;

    const int arow = tid >> 1;
    const int aseg = (tid & 1) * 4;
    const int brow = tid >> 5;
    const int bcol = (tid & 31) * 4;

    for (int k0 = 0; k0 < K; k0 += BK) {
        float4 av = *(const float4*)(A + (size_t)(m0 + arow) * K + k0 + aseg);
        As[aseg + 0][arow] = av.x;
        As[aseg + 1][arow] = av.y;
        As[aseg + 2][arow] = av.z;
        As[aseg + 3][arow] = av.w;
        float4 bv = *(const float4*)(B + (size_t)(k0 + brow) * N + n0 + bcol);
        *(float4*)(&Bs[brow][bcol]) = bv;
        __syncthreads();
#pragma unroll
        for (int kk = 0; kk < BK; kk++) {
            float a[TM], b[TN];
#pragma unroll
            for (int i = 0; i < TM; i++) a[i] = As[kk][ty * TM + i];
#pragma unroll
            for (int j = 0; j < TN; j++) b[j] = Bs[kk][tx * TN + j];
#pragma unroll
            for (int i = 0; i < TM; i++)
#pragma unroll
                for (int j = 0; j < TN; j++) acc[i][j] += a[i] * b[j];
        }
        __syncthreads();
    }
#pragma unroll
    for (int i = 0; i < TM; i++) {
        const int m = m0 + ty * TM + i;
#pragma unroll
        for (int j = 0; j < TN; j += 4) {
            const int n = n0 + tx * TN + j;
            float4 o;
            o.x = acc[i][j + 0] + bias[n + 0];
            o.y = acc[i][j + 1] + bias[n + 1];
            o.z = acc[i][j + 2] + bias[n + 2];
            o.w = acc[i][j + 3] + bias[n + 3];
            *(float4*)(C + (size_t)m * N + n) = o;
        }
    }
}

// ============ Batched GEMM-NT: C[z] = A[z][M,K] * B[z][N,K]^T ============
__global__ __launch_bounds__(256) void gemm_nt_batched(
    const float* __restrict__ Ag, const float* __restrict__ Bg,
    float* __restrict__ Cg, int M, int N, int K)
{
    const float* A = Ag + (size_t)blockIdx.z * M * K;
    const float* B = Bg + (size_t)blockIdx.z * N * K;
    float* C = Cg + (size_t)blockIdx.z * M * N;

    __shared__ float As[BK][BM];
    __shared__ float Bs[BK][BN];
    const int tid = threadIdx.x;
    const int m0 = blockIdx.y * BM;
    const int n0 = blockIdx.x * BN;
    const int tx = tid & 15;
    const int ty = tid >> 4;

    float acc[TM][TN];
#pragma unroll
    for (int i = 0; i < TM; i++)
#pragma unroll
        for (int j = 0; j < TN; j++) acc[i][j] = 0.f;

    const int arow = tid >> 1;
    const int aseg = (tid & 1) * 4;

    for (int k0 = 0; k0 < K; k0 += BK) {
        float4 av = *(const float4*)(A + (size_t)(m0 + arow) * K + k0 + aseg);
        As[aseg + 0][arow] = av.x;
        As[aseg + 1][arow] = av.y;
        As[aseg + 2][arow] = av.z;
        As[aseg + 3][arow] = av.w;
        float4 bv = *(const float4*)(B + (size_t)(n0 + arow) * K + k0 + aseg);
        Bs[aseg + 0][arow] = bv.x;
        Bs[aseg + 1][arow] = bv.y;
        Bs[aseg + 2][arow] = bv.z;
        Bs[aseg + 3][arow] = bv.w;
        __syncthreads();
#pragma unroll
        for (int kk = 0; kk < BK; kk++) {
            float a[TM], b[TN];
#pragma unroll
            for (int i = 0; i < TM; i++) a[i] = As[kk][ty * TM + i];
#pragma unroll
            for (int j = 0; j < TN; j++) b[j] = Bs[kk][tx * TN + j];
#pragma unroll
            for (int i = 0; i < TM; i++)
#pragma unroll
                for (int j = 0; j < TN; j++) acc[i][j] += a[i] * b[j];
        }
        __syncthreads();
    }
#pragma unroll
    for (int i = 0; i < TM; i++) {
        const int m = m0 + ty * TM + i;
#pragma unroll
        for (int j = 0; j < TN; j += 4) {
            const int n = n0 + tx * TN + j;
            float4 o;
            o.x = acc[i][j + 0];
            o.y = acc[i][j + 1];
            o.z = acc[i][j + 2];
            o.w = acc[i][j + 3];
            *(float4*)(C + (size_t)m * N + n) = o;
        }
    }
}

// ==== Batched GEMM-NN + residual: C[z] = A[z][M,K]*B[z][K,N] + R[z] ====
__global__ __launch_bounds__(256) void gemm_nn_res_batched(
    const float* __restrict__ Ag, const float* __restrict__ Bg,
    const float* __restrict__ Rg, float* __restrict__ Cg,
    int M, int N, int K)
{
    const float* A = Ag + (size_t)blockIdx.z * M * K;
    const float* B = Bg + (size_t)blockIdx.z * K * N;
    const float* R = Rg + (size_t)blockIdx.z * M * N;
    float* C = Cg + (size_t)blockIdx.z * M * N;

    __shared__ float As[BK][BM];
    __shared__ float Bs[BK][BN];
    const int tid = threadIdx.x;
    const int m0 = blockIdx.y * BM;
    const int n0 = blockIdx.x * BN;
    const int tx = tid & 15;
    const int ty = tid >> 4;

    float acc[TM][TN];
#pragma unroll
    for (int i = 0; i < TM; i++)
#pragma unroll
        for (int j = 0; j < TN; j++) acc[i][j] = 0.f;

    const int arow = tid >> 1;
    const int aseg = (tid & 1) * 4;
    const int brow = tid >> 5;
    const int bcol = (tid & 31) * 4;

    for (int k0 = 0; k0 < K; k0 += BK) {
        float4 av = *(const float4*)(A + (size_t)(m0 + arow) * K + k0 + aseg);
        As[aseg + 0][arow] = av.x;
        As[aseg + 1][arow] = av.y;
        As[aseg + 2][arow] = av.z;
        As[aseg + 3][arow] = av.w;
        float4 bv = *(const float4*)(B + (size_t)(k0 + brow) * N + n0 + bcol);
        *(float4*)(&Bs[brow][bcol]) = bv;
        __syncthreads();
#pragma unroll
        for (int kk = 0; kk < BK; kk++) {
            float a[TM], b[TN];
#pragma unroll
            for (int i = 0; i < TM; i++) a[i] = As[kk][ty * TM + i];
#pragma unroll
            for (int j = 0; j < TN; j++) b[j] = Bs[kk][tx * TN + j];
#pragma unroll
            for (int i = 0; i < TM; i++)
#pragma unroll
                for (int j = 0; j < TN; j++) acc[i][j] += a[i] * b[j];
        }
        __syncthreads();
    }
#pragma unroll
    for (int i = 0; i < TM; i++) {
        const int m = m0 + ty * TM + i;
#pragma unroll
        for (int j = 0; j < TN; j += 4) {
            const int n = n0 + tx * TN + j;
            float4 r = *(const float4*)(R + (size_t)m * N + n);
            float4 o;
            o.x = acc[i][j + 0] + r.x;
            o.y = acc[i][j + 1] + r.y;
            o.z = acc[i][j + 2] + r.z;
            o.w = acc[i][j + 3] + r.w;
            *(float4*)(C + (size_t)m * N + n) = o;
        }
    }
}

// ===================== LayerNorm over rows of width 512 =====================
__global__ __launch_bounds__(256) void layernorm_rows512(
    float* __restrict__ X, const float* __restrict__ gam,
    const float* __restrict__ bet)
{
    float* row = X + (size_t)blockIdx.x * 512;
    const int tid = threadIdx.x;
    float v0 = row[tid];
    float v1 = row[tid + 256];

    __shared__ float sred[8];
    float s = v0 + v1;
#pragma unroll
    for (int o = 16; o; o >>= 1) s += __shfl_xor_sync(0xffffffffu, s, o);
    if ((tid & 31) == 0) sred[tid >> 5] = s;
    __syncthreads();
    float tot = 0.f;
#pragma unroll
    for (int i = 0; i < 8; i++) tot += sred[i];
    const float mean = tot * (1.0f / 512.0f);

    const float d0 = v0 - mean, d1 = v1 - mean;
    float q = d0 * d0 + d1 * d1;
#pragma unroll
    for (int o = 16; o; o >>= 1) q += __shfl_xor_sync(0xffffffffu, q, o);
    __syncthreads();
    if ((tid & 31) == 0) sred[tid >> 5] = q;
    __syncthreads();
    float qt = 0.f;
#pragma unroll
    for (int i = 0; i < 8; i++) qt += sred[i];
    const float rstd = rsqrtf(qt * (1.0f / 512.0f) + 1e-5f);

    row[tid]       = d0 * rstd * gam[tid]       + bet[tid];
    row[tid + 256] = d1 * rstd * gam[tid + 256] + bet[tid + 256];
}

// ===================== Row softmax over width 2048 =====================
__global__ __launch_bounds__(256) void softmax_rows2048(float* __restrict__ S)
{
    float* row = S + (size_t)blockIdx.x * 2048;
    const int tid = threadIdx.x;
    __shared__ float sred[8];

    float vals[8];
    float lmax = -CUDART_INF_F;
#pragma unroll
    for (int i = 0; i < 8; i++) {
        vals[i] = row[tid + i * 256];
        lmax = fmaxf(lmax, vals[i]);
    }
#pragma unroll
    for (int o = 16; o; o >>= 1) lmax = fmaxf(lmax, __shfl_xor_sync(0xffffffffu, lmax, o));
    if ((tid & 31) == 0) sred[tid >> 5] = lmax;
    __syncthreads();
    float m = sred[0];
#pragma unroll
    for (int i = 1; i < 8; i++) m = fmaxf(m, sred[i]);

    float lsum = 0.f;
#pragma unroll
    for (int i = 0; i < 8; i++) {
        vals[i] = __expf(vals[i] - m);
        lsum += vals[i];
    }
#pragma unroll
    for (int o = 16; o; o >>= 1) lsum += __shfl_xor_sync(0xffffffffu, lsum, o);
    __syncthreads();
    if ((tid & 31) == 0) sred[tid >> 5] = lsum;
    __syncthreads();
    float tot = 0.f;
#pragma unroll
    for (int i = 0; i < 8; i++) tot += sred[i];
    const float inv = 1.0f / tot;
#pragma unroll
    for (int i = 0; i < 8; i++) row[tid + i * 256] = vals[i] * inv;
}

// ===================== launch =====================
extern "C" void kernel_launch(void* const* d_in, const int* in_sizes, int n_in,
                              void* d_out, int out_size)
{
    const float* q_seq = (const float*)d_in[0];   // [8,2048,512]
    const float* kv    = (const float*)d_in[1];   // [8,2048,768]
    const float* Wq    = (const float*)d_in[2];   // [512,512]
    const float* bq    = (const float*)d_in[3];
    const float* gq    = (const float*)d_in[4];
    const float* betaq = (const float*)d_in[5];
    const float* Wk    = (const float*)d_in[6];   // [768,512]
    const float* bk    = (const float*)d_in[7];
    const float* gk    = (const float*)d_in[8];
    const float* betak = (const float*)d_in[9];
    const float* Wv    = (const float*)d_in[10];  // [768,512]
    const float* bv    = (const float*)d_in[11];
    const float* gv    = (const float*)d_in[12];
    const float* betav = (const float*)d_in[13];
    float* out = (float*)d_out;

    float *Qp, *Kp, *Vp, *Sp;
    cudaGetSymbolAddress((void**)&Qp, g_Q);
    cudaGetSymbolAddress((void**)&Kp, g_K);
    cudaGetSymbolAddress((void**)&Vp, g_V);
    cudaGetSymbolAddress((void**)&Sp, g_S);

    const dim3 projGrid(HDIM / BN, MROWS / BM);       // (4, 128)
    const dim3 sGrid(SEQ / BN, SEQ / BM, BATCH);      // (16, 16, 8)
    const dim3 oGrid(DQ / BN, SEQ / BM, BATCH);       // (4, 16, 8)

    // Projections + LayerNorm
    gemm_bias_nn<<<projGrid, 256>>>(q_seq, Wq, bq, Qp, MROWS, HDIM, DQ);
    layernorm_rows512<<<MROWS, 256>>>(Qp, gq, betaq);

    gemm_bias_nn<<<projGrid, 256>>>(kv, Wk, bk, Kp, MROWS, HDIM, DKV);
    layernorm_rows512<<<MROWS, 256>>>(Kp, gk, betak);

    gemm_bias_nn<<<projGrid, 256>>>(kv, Wv, bv, Vp, MROWS, DQ, DKV);
    layernorm_rows512<<<MROWS, 256>>>(Vp, gv, betav);

    // Scores S[b] = K[b] (2048x512) * Q[b]^T (512x2048)
    gemm_nt_batched<<<sGrid, 256>>>(Kp, Qp, Sp, SEQ, SEQ, HDIM);

    // Row softmax over last axis
    softmax_rows2048<<<BATCH * SEQ, 256>>>(Sp);

    // Output O[b] = P[b] (2048x2048) * V[b] (2048x512) + q_seq[b]
    gemm_nn_res_batched<<<oGrid, 256>>>(Sp, Vp, q_seq, out, SEQ, DQ, SEQ);
}

// round 3
// speedup vs baseline: 2.2742x; 2.2742x over previous
#include <cuda_runtime.h>
#include <cuda_bf16.h>
#include <cstdint>
#include <math_constants.h>

// ============================ problem shapes ============================
#define BATCH 8
#define SEQ   2048
#define DQ    512
#define DKV   768
#define HDIM  512
#define MROWS (BATCH*SEQ)   // 16384

// ============================ device scratch ============================
__device__ __nv_bfloat16 g_Xh[(size_t)MROWS*DQ],  g_Xl[(size_t)MROWS*DQ];
__device__ __nv_bfloat16 g_KVh[(size_t)MROWS*DKV], g_KVl[(size_t)MROWS*DKV];
__device__ __nv_bfloat16 g_Wqh[HDIM*DQ],  g_Wql[HDIM*DQ];    // WqT [512,512]
__device__ __nv_bfloat16 g_Wkh[HDIM*DKV], g_Wkl[HDIM*DKV];   // WkT [512,768]
__device__ __nv_bfloat16 g_Wvh[DQ*DKV],   g_Wvl[DQ*DKV];     // WvT [512,768]
__device__ float         g_F[(size_t)MROWS*HDIM];            // proj fp32 scratch
__device__ __nv_bfloat16 g_Qh[(size_t)MROWS*HDIM], g_Ql[(size_t)MROWS*HDIM];
__device__ __nv_bfloat16 g_Kh[(size_t)MROWS*HDIM], g_Kl[(size_t)MROWS*HDIM];
__device__ __nv_bfloat16 g_Vth[(size_t)BATCH*DQ*SEQ], g_Vtl[(size_t)BATCH*DQ*SEQ];
__device__ float         g_S[(size_t)BATCH*SEQ*SEQ];
__device__ __nv_bfloat16 g_Ph[(size_t)BATCH*SEQ*SEQ], g_Pl[(size_t)BATCH*SEQ*SEQ];

// ============================ GEMM config ============================
// CTA tile 128x128, K-tile 32 (bf16), 3 stages, 256 threads (8 warps, 2m x 4n).
// SMEM per tile: 128 rows x 40 bf16 (80B, padded from 64B) = 10240 B.
// Stage = Ah,Al,Bh,Bl = 40960 B. 3 stages = 122880 B.
#define ROWPAD   40           // bf16 elems per smem row (20 words)
#define TILE_B   10240
#define STAGE_B  40960
#define NSTAGE   3
#define GEMM_SMEM (NSTAGE*STAGE_B)

__device__ __forceinline__ uint32_t smem_u32(const void* p) {
    uint32_t a;
    asm("{ .reg .u64 t; cvta.to.shared.u64 t, %1; cvt.u32.u64 %0, t; }" : "=r"(a) : "l"(p));
    return a;
}

__device__ __forceinline__ void cp16(uint32_t sa, const void* ga) {
    asm volatile("cp.async.cg.shared.global [%0], [%1], 16;\n" :: "r"(sa), "l"(ga));
}

__device__ __forceinline__ void mma_bf16(float& c0, float& c1, float& c2, float& c3,
                                         uint32_t a0, uint32_t a1, uint32_t a2, uint32_t a3,
                                         uint32_t b0, uint32_t b1) {
    asm volatile(
        "mma.sync.aligned.m16n8k16.row.col.f32.bf16.bf16.f32 "
        "{%0,%1,%2,%3}, {%4,%5,%6,%7}, {%8,%9}, {%0,%1,%2,%3};\n"
        : "+f"(c0), "+f"(c1), "+f"(c2), "+f"(c3)
        : "r"(a0), "r"(a1), "r"(a2), "r"(a3), "r"(b0), "r"(b1));
}

// load one stage: Ah/Al rows [aRow0,+128), Bh/Bl rows [bRow0,+128), k window [k0,k0+32)
__device__ __forceinline__ void load_stage(
    uint32_t sstage,
    const __nv_bfloat16* __restrict__ Ah, const __nv_bfloat16* __restrict__ Al,
    size_t aRow0, int lda,
    const __nv_bfloat16* __restrict__ Bh, const __nv_bfloat16* __restrict__ Bl,
    size_t bRow0, int ldb, int k0, int tid)
{
    // 2048 chunks of 16B: tile=i>>9, r=(i>>2)&127, c=i&3
#pragma unroll
    for (int j = 0; j < 8; j++) {
        const int i = tid + j * 256;
        const int tile = i >> 9;
        const int r = (i >> 2) & 127;
        const int c = i & 3;
        const __nv_bfloat16* gp;
        if (tile == 0)      gp = Ah + (aRow0 + r) * (size_t)lda + k0 + c * 8;
        else if (tile == 1) gp = Al + (aRow0 + r) * (size_t)lda + k0 + c * 8;
        else if (tile == 2) gp = Bh + (bRow0 + r) * (size_t)ldb + k0 + c * 8;
        else                gp = Bl + (bRow0 + r) * (size_t)ldb + k0 + c * 8;
        cp16(sstage + tile * TILE_B + r * (ROWPAD * 2) + c * 16, gp);
    }
}

// C[128x128 tile] = sum_k (Ah+Al)[m,k]*(Bh+Bl)[n,k]  (3-pass bf16, fp32 accum)
__global__ void __launch_bounds__(256, 1) gemm3x_mma(
    const __nv_bfloat16* __restrict__ Ah, const __nv_bfloat16* __restrict__ Al, int lda, int aBatch,
    const __nv_bfloat16* __restrict__ Bh, const __nv_bfloat16* __restrict__ Bl, int ldb, int bBatch,
    float* __restrict__ C, int ldc, int cBatch,
    const float* __restrict__ bias, const float* __restrict__ Res,
    int Ktot, int epi)   // epi: 0 none, 1 +bias[n], 2 +Res[m,n]
{
    extern __shared__ char smem[];
    const uint32_t sb = smem_u32(smem);
    const uint32_t* SW = (const uint32_t*)smem;

    const int tid  = threadIdx.x;
    const int wid  = tid >> 5;
    const int lane = tid & 31;
    const int g    = lane >> 2;     // groupID 0..7
    const int t4   = lane & 3;      // thread-in-group
    const int wm   = wid & 1;       // 0..1 (m)
    const int wn   = wid >> 1;      // 0..3 (n)

    const size_t aRow0 = (size_t)blockIdx.z * aBatch + (size_t)blockIdx.y * 128;
    const size_t bRow0 = (size_t)blockIdx.z * bBatch + (size_t)blockIdx.x * 128;

    float acc[4][4][4];
#pragma unroll
    for (int mt = 0; mt < 4; mt++)
#pragma unroll
        for (int nt = 0; nt < 4; nt++)
#pragma unroll
            for (int r = 0; r < 4; r++) acc[mt][nt][r] = 0.f;

    const int nkb = Ktot >> 5;

    // prologue: stages 0,1
    load_stage(sb, Ah, Al, aRow0, lda, Bh, Bl, bRow0, ldb, 0, tid);
    asm volatile("cp.async.commit_group;\n" ::: "memory");
    load_stage(sb + STAGE_B, Ah, Al, aRow0, lda, Bh, Bl, bRow0, ldb, 32, tid);
    asm volatile("cp.async.commit_group;\n" ::: "memory");

    for (int kb = 0; kb < nkb; kb++) {
        __syncthreads();  // everyone done reading the slot we are about to overwrite
        if (kb + 2 < nkb) {
            const int s = (kb + 2) % NSTAGE;
            load_stage(sb + s * STAGE_B, Ah, Al, aRow0, lda, Bh, Bl, bRow0, ldb,
                       (kb + 2) << 5, tid);
        }
        asm volatile("cp.async.commit_group;\n" ::: "memory");
        asm volatile("cp.async.wait_group 2;\n" ::: "memory");
        __syncthreads();  // stage kb visible to all

        const int slot = kb % NSTAGE;
        const uint32_t* AhW = SW + slot * (STAGE_B / 4);
        const uint32_t* AlW = AhW + TILE_B / 4;
        const uint32_t* BhW = AhW + 2 * (TILE_B / 4);
        const uint32_t* BlW = AhW + 3 * (TILE_B / 4);

#pragma unroll
        for (int ks = 0; ks < 2; ks++) {
            const int kw = ks * 8 + t4;   // word col
            uint32_t ah[4][4], al[4][4], bh[4][2], bl[4][2];
#pragma unroll
            for (int mt = 0; mt < 4; mt++) {
                const int r0 = (wm * 64 + mt * 16 + g) * (ROWPAD / 2);
                ah[mt][0] = AhW[r0 + kw];
                ah[mt][1] = AhW[r0 + 160 + kw];      // row +8 (8*20 words)
                ah[mt][2] = AhW[r0 + kw + 4];
                ah[mt][3] = AhW[r0 + 160 + kw + 4];
                al[mt][0] = AlW[r0 + kw];
                al[mt][1] = AlW[r0 + 160 + kw];
                al[mt][2] = AlW[r0 + kw + 4];
                al[mt][3] = AlW[r0 + 160 + kw + 4];
            }
#pragma unroll
            for (int nt = 0; nt < 4; nt++) {
                const int r0 = (wn * 32 + nt * 8 + g) * (ROWPAD / 2);
                bh[nt][0] = BhW[r0 + kw];
                bh[nt][1] = BhW[r0 + kw + 4];
                bl[nt][0] = BlW[r0 + kw];
                bl[nt][1] = BlW[r0 + kw + 4];
            }
#pragma unroll
            for (int mt = 0; mt < 4; mt++)
#pragma unroll
                for (int nt = 0; nt < 4; nt++) {
                    float* c = acc[mt][nt];
                    mma_bf16(c[0], c[1], c[2], c[3],
                             ah[mt][0], ah[mt][1], ah[mt][2], ah[mt][3],
                             bh[nt][0], bh[nt][1]);
                    mma_bf16(c[0], c[1], c[2], c[3],
                             ah[mt][0], ah[mt][1], ah[mt][2], ah[mt][3],
                             bl[nt][0], bl[nt][1]);
                    mma_bf16(c[0], c[1], c[2], c[3],
                             al[mt][0], al[mt][1], al[mt][2], al[mt][3],
                             bh[nt][0], bh[nt][1]);
                }
        }
    }

    // -------- epilogue: registers -> global (fused bias / residual) --------
    const size_t cRow0 = (size_t)blockIdx.z * cBatch + (size_t)blockIdx.y * 128;
    const int n0 = blockIdx.x * 128 + wn * 32;
#pragma unroll
    for (int mt = 0; mt < 4; mt++) {
#pragma unroll
        for (int nt = 0; nt < 4; nt++) {
            const int m = wm * 64 + mt * 16 + g;
            const int n = n0 + nt * 8 + t4 * 2;
            float v0 = acc[mt][nt][0], v1 = acc[mt][nt][1];
            float v2 = acc[mt][nt][2], v3 = acc[mt][nt][3];
            const size_t i0 = (cRow0 + m) * (size_t)ldc + n;
            const size_t i1 = (cRow0 + m + 8) * (size_t)ldc + n;
            if (epi == 1) {
                const float b0 = bias[n], b1 = bias[n + 1];
                v0 += b0; v1 += b1; v2 += b0; v3 += b1;
            } else if (epi == 2) {
                const float2 r0 = *(const float2*)(Res + i0);
                const float2 r1 = *(const float2*)(Res + i1);
                v0 += r0.x; v1 += r0.y; v2 += r1.x; v3 += r1.y;
            }
            float2 o0; o0.x = v0; o0.y = v1;
            float2 o1; o1.x = v2; o1.y = v3;
            *(float2*)(C + i0) = o0;
            *(float2*)(C + i1) = o1;
        }
    }
}

// ======================= elementwise / helper kernels =======================
__device__ __forceinline__ void split_bf16(float x, __nv_bfloat16& h, __nv_bfloat16& l) {
    h = __float2bfloat16_rn(x);
    l = __float2bfloat16_rn(x - __bfloat162float(h));
}

__global__ __launch_bounds__(256) void convert_hilo(
    const float4* __restrict__ in, __nv_bfloat162* __restrict__ hi,
    __nv_bfloat162* __restrict__ lo, int n4)
{
    int i = blockIdx.x * 256 + threadIdx.x;
    if (i >= n4) return;
    float4 v = in[i];
    __nv_bfloat16 h0, l0, h1, l1, h2, l2, h3, l3;
    split_bf16(v.x, h0, l0); split_bf16(v.y, h1, l1);
    split_bf16(v.z, h2, l2); split_bf16(v.w, h3, l3);
    hi[2 * i]     = __nv_bfloat162(h0, h1);
    hi[2 * i + 1] = __nv_bfloat162(h2, h3);
    lo[2 * i]     = __nv_bfloat162(l0, l1);
    lo[2 * i + 1] = __nv_bfloat162(l2, l3);
}

// Transpose + split: out[c][r] = in[r][c]
__global__ void transpose_convert(
    const float* __restrict__ in, size_t inBatch, int ldin,
    __nv_bfloat16* __restrict__ oh, __nv_bfloat16* __restrict__ ol,
    size_t outBatch, int ldout)
{
    __shared__ float t[32][33];
    const int r0 = blockIdx.x * 32, c0 = blockIdx.y * 32, z = blockIdx.z;
    const float* ip = in + (size_t)z * inBatch;
#pragma unroll
    for (int j = 0; j < 32; j += 8)
        t[threadIdx.y + j][threadIdx.x] =
            ip[(size_t)(r0 + threadIdx.y + j) * ldin + c0 + threadIdx.x];
    __syncthreads();
#pragma unroll
    for (int j = 0; j < 32; j += 8) {
        float v = t[threadIdx.x][threadIdx.y + j];
        __nv_bfloat16 h, l; split_bf16(v, h, l);
        size_t oidx = (size_t)z * outBatch + (size_t)(c0 + threadIdx.y + j) * ldout + r0 + threadIdx.x;
        oh[oidx] = h; ol[oidx] = l;
    }
}

// LayerNorm rows of 512; out bf16 hi/lo (if oh) else fp32 in place
__global__ __launch_bounds__(256) void ln512(
    float* __restrict__ X, const float* __restrict__ gam, const float* __restrict__ bet,
    __nv_bfloat16* __restrict__ oh, __nv_bfloat16* __restrict__ ol)
{
    float* row = X + (size_t)blockIdx.x * 512;
    const int tid = threadIdx.x;
    float v0 = row[tid], v1 = row[tid + 256];
    __shared__ float sred[8];
    float s = v0 + v1;
#pragma unroll
    for (int o = 16; o; o >>= 1) s += __shfl_xor_sync(0xffffffffu, s, o);
    if ((tid & 31) == 0) sred[tid >> 5] = s;
    __syncthreads();
    float tot = 0.f;
#pragma unroll
    for (int i = 0; i < 8; i++) tot += sred[i];
    const float mean = tot * (1.0f / 512.0f);
    const float d0 = v0 - mean, d1 = v1 - mean;
    float q = d0 * d0 + d1 * d1;
#pragma unroll
    for (int o = 16; o; o >>= 1) q += __shfl_xor_sync(0xffffffffu, q, o);
    __syncthreads();
    if ((tid & 31) == 0) sred[tid >> 5] = q;
    __syncthreads();
    float qt = 0.f;
#pragma unroll
    for (int i = 0; i < 8; i++) qt += sred[i];
    const float rstd = rsqrtf(qt * (1.0f / 512.0f) + 1e-5f);
    float r0 = d0 * rstd * gam[tid] + bet[tid];
    float r1 = d1 * rstd * gam[tid + 256] + bet[tid + 256];
    if (oh) {
        __nv_bfloat16 h, l;
        size_t base = (size_t)blockIdx.x * 512;
        split_bf16(r0, h, l); oh[base + tid] = h;       ol[base + tid] = l;
        split_bf16(r1, h, l); oh[base + tid + 256] = h; ol[base + tid + 256] = l;
    } else {
        row[tid] = r0; row[tid + 256] = r1;
    }
}

// Row softmax over 2048 + bf16 hi/lo split output
__global__ __launch_bounds__(256) void softmax_convert(
    const float* __restrict__ S, __nv_bfloat16* __restrict__ Ph, __nv_bfloat16* __restrict__ Pl)
{
    const float* row = S + (size_t)blockIdx.x * 2048;
    const int tid = threadIdx.x;
    __shared__ float sred[8];
    float vals[8];
    float lmax = -CUDART_INF_F;
#pragma unroll
    for (int i = 0; i < 8; i++) {
        vals[i] = row[tid + i * 256];
        lmax = fmaxf(lmax, vals[i]);
    }
#pragma unroll
    for (int o = 16; o; o >>= 1) lmax = fmaxf(lmax, __shfl_xor_sync(0xffffffffu, lmax, o));
    if ((tid & 31) == 0) sred[tid >> 5] = lmax;
    __syncthreads();
    float m = sred[0];
#pragma unroll
    for (int i = 1; i < 8; i++) m = fmaxf(m, sred[i]);
    float lsum = 0.f;
#pragma unroll
    for (int i = 0; i < 8; i++) { vals[i] = __expf(vals[i] - m); lsum += vals[i]; }
#pragma unroll
    for (int o = 16; o; o >>= 1) lsum += __shfl_xor_sync(0xffffffffu, lsum, o);
    __syncthreads();
    if ((tid & 31) == 0) sred[tid >> 5] = lsum;
    __syncthreads();
    float tot = 0.f;
#pragma unroll
    for (int i = 0; i < 8; i++) tot += sred[i];
    const float inv = 1.0f / tot;
    const size_t base = (size_t)blockIdx.x * 2048;
#pragma unroll
    for (int i = 0; i < 8; i++) {
        float p = vals[i] * inv;
        __nv_bfloat16 h, l; split_bf16(p, h, l);
        Ph[base + tid + i * 256] = h;
        Pl[base + tid + i * 256] = l;
    }
}

// ============================ launch ============================
extern "C" void kernel_launch(void* const* d_in, const int* in_sizes, int n_in,
                              void* d_out, int out_size)
{
    const float* q_seq = (const float*)d_in[0];
    const float* kv    = (const float*)d_in[1];
    const float* Wq    = (const float*)d_in[2];
    const float* bq    = (const float*)d_in[3];
    const float* gq    = (const float*)d_in[4];
    const float* betaq = (const float*)d_in[5];
    const float* Wk    = (const float*)d_in[6];
    const float* bk    = (const float*)d_in[7];
    const float* gk    = (const float*)d_in[8];
    const float* betak = (const float*)d_in[9];
    const float* Wv    = (const float*)d_in[10];
    const float* bv    = (const float*)d_in[11];
    const float* gv    = (const float*)d_in[12];
    const float* betav = (const float*)d_in[13];
    float* out = (float*)d_out;

    __nv_bfloat16 *Xh, *Xl, *KVh, *KVl, *Wqh, *Wql, *Wkh, *Wkl, *Wvh, *Wvl;
    __nv_bfloat16 *Qh, *Ql, *Kh, *Kl, *Vth, *Vtl, *Ph, *Pl;
    float *F, *S;
    cudaGetSymbolAddress((void**)&Xh, g_Xh);   cudaGetSymbolAddress((void**)&Xl, g_Xl);
    cudaGetSymbolAddress((void**)&KVh, g_KVh); cudaGetSymbolAddress((void**)&KVl, g_KVl);
    cudaGetSymbolAddress((void**)&Wqh, g_Wqh); cudaGetSymbolAddress((void**)&Wql, g_Wql);
    cudaGetSymbolAddress((void**)&Wkh, g_Wkh); cudaGetSymbolAddress((void**)&Wkl, g_Wkl);
    cudaGetSymbolAddress((void**)&Wvh, g_Wvh); cudaGetSymbolAddress((void**)&Wvl, g_Wvl);
    cudaGetSymbolAddress((void**)&Qh, g_Qh);   cudaGetSymbolAddress((void**)&Ql, g_Ql);
    cudaGetSymbolAddress((void**)&Kh, g_Kh);   cudaGetSymbolAddress((void**)&Kl, g_Kl);
    cudaGetSymbolAddress((void**)&Vth, g_Vth); cudaGetSymbolAddress((void**)&Vtl, g_Vtl);
    cudaGetSymbolAddress((void**)&Ph, g_Ph);   cudaGetSymbolAddress((void**)&Pl, g_Pl);
    cudaGetSymbolAddress((void**)&F, g_F);     cudaGetSymbolAddress((void**)&S, g_S);

    cudaFuncSetAttribute(gemm3x_mma, cudaFuncAttributeMaxDynamicSharedMemorySize, GEMM_SMEM);

    const dim3 tb(32, 8);

    // 1) split inputs into bf16 hi/lo
    convert_hilo<<<(MROWS * DQ / 4 + 255) / 256, 256>>>(
        (const float4*)q_seq, (__nv_bfloat162*)Xh, (__nv_bfloat162*)Xl, MROWS * DQ / 4);
    convert_hilo<<<(MROWS * DKV / 4 + 255) / 256, 256>>>(
        (const float4*)kv, (__nv_bfloat162*)KVh, (__nv_bfloat162*)KVl, MROWS * DKV / 4);

    // 2) transpose + split weights: W[K,N] -> WT[N,K]
    transpose_convert<<<dim3(DQ / 32, HDIM / 32, 1), tb>>>(Wq, 0, HDIM, Wqh, Wql, 0, DQ);
    transpose_convert<<<dim3(DKV / 32, HDIM / 32, 1), tb>>>(Wk, 0, HDIM, Wkh, Wkl, 0, DKV);
    transpose_convert<<<dim3(DKV / 32, DQ / 32, 1), tb>>>(Wv, 0, DQ, Wvh, Wvl, 0, DKV);

    // 3) Q projection + LN -> bf16 hi/lo
    gemm3x_mma<<<dim3(HDIM / 128, MROWS / 128, 1), 256, GEMM_SMEM>>>(
        Xh, Xl, DQ, 0, Wqh, Wql, DQ, 0, F, HDIM, 0, bq, nullptr, DQ, 1);
    ln512<<<MROWS, 256>>>(F, gq, betaq, Qh, Ql);

    // 4) K projection + LN -> bf16 hi/lo
    gemm3x_mma<<<dim3(HDIM / 128, MROWS / 128, 1), 256, GEMM_SMEM>>>(
        KVh, KVl, DKV, 0, Wkh, Wkl, DKV, 0, F, HDIM, 0, bk, nullptr, DKV, 1);
    ln512<<<MROWS, 256>>>(F, gk, betak, Kh, Kl);

    // 5) V projection + LN (fp32), then transpose+split -> Vt [b*512+c, 2048]
    gemm3x_mma<<<dim3(DQ / 128, MROWS / 128, 1), 256, GEMM_SMEM>>>(
        KVh, KVl, DKV, 0, Wvh, Wvl, DKV, 0, F, DQ, 0, bv, nullptr, DKV, 1);
    ln512<<<MROWS, 256>>>(F, gv, betav, nullptr, nullptr);
    transpose_convert<<<dim3(SEQ / 32, DQ / 32, BATCH), tb>>>(
        F, (size_t)SEQ * DQ, DQ, Vth, Vtl, (size_t)DQ * SEQ, SEQ);

    // 6) scores S[b,l,L] = K[b,l,:] . Q[b,L,:]
    gemm3x_mma<<<dim3(SEQ / 128, SEQ / 128, BATCH), 256, GEMM_SMEM>>>(
        Kh, Kl, HDIM, SEQ, Qh, Ql, HDIM, SEQ, S, SEQ, SEQ, nullptr, nullptr, HDIM, 0);

    // 7) softmax + split -> P hi/lo
    softmax_convert<<<BATCH * SEQ, 256>>>(S, Ph, Pl);

    // 8) out[b,l,c] = sum_L P[l,L]*Vt[c,L] + q_seq
    gemm3x_mma<<<dim3(DQ / 128, SEQ / 128, BATCH), 256, GEMM_SMEM>>>(
        Ph, Pl, SEQ, SEQ, Vth, Vtl, SEQ, DQ, out, DQ, SEQ, nullptr, q_seq, SEQ, 2);
}